// round 1
// baseline (speedup 1.0000x reference)
#include <cuda_runtime.h>
#include <cuda_bf16.h>
#include <math.h>

// Problem constants
#define BB   2
#define SS   1024
#define PP   1024
#define TT   (PP + SS)
#define HH   4096
#define NQ   32
#define NKV  8
#define DD   128
#define GG   (NQ / NKV)
#define QKVN ((NQ + 2 * NKV) * DD)   // 6144
#define SCALE 0.08838834764831845f   // 1/sqrt(128)

// Scratch (device globals: no allocation allowed)
__device__ float g_qkv[BB * SS * QKVN];      // 50 MB
__device__ float g_attn[BB * SS * NQ * DD];  // 33 MB

// ---------------------------------------------------------------------------
// SGEMM: C[M,N] = A[M,K] @ B[K,N], row-major, all dims multiples of 128/16.
// 128x128 block tile, BK=16, 256 threads, 8x8 micro-tile (split 4+4).
// ---------------------------------------------------------------------------
__global__ __launch_bounds__(256) void sgemm128(
    const float* __restrict__ A, const float* __restrict__ B,
    float* __restrict__ C, int M, int N, int K)
{
    __shared__ float As[16][128];   // k-major (transposed A tile)
    __shared__ float Bs[16][128];

    const int tid = threadIdx.x;
    const int tx = tid & 15, ty = tid >> 4;
    const int bm = blockIdx.y * 128, bn = blockIdx.x * 128;

    float acc[8][8];
#pragma unroll
    for (int i = 0; i < 8; i++)
#pragma unroll
        for (int j = 0; j < 8; j++) acc[i][j] = 0.f;

    for (int kt = 0; kt < K; kt += 16) {
#pragma unroll
        for (int i = 0; i < 2; i++) {
            int id = tid + i * 256;               // 0..511
            int arow = id >> 2, acol = (id & 3) << 2;
            float4 av = *(const float4*)&A[(size_t)(bm + arow) * K + kt + acol];
            As[acol + 0][arow] = av.x;
            As[acol + 1][arow] = av.y;
            As[acol + 2][arow] = av.z;
            As[acol + 3][arow] = av.w;
            int brow = id >> 5, bcol = (id & 31) << 2;
            *(float4*)&Bs[brow][bcol] =
                *(const float4*)&B[(size_t)(kt + brow) * N + bn + bcol];
        }
        __syncthreads();
#pragma unroll
        for (int kk = 0; kk < 16; kk++) {
            float a[8], b[8];
            *(float4*)&a[0] = *(float4*)&As[kk][ty * 4];
            *(float4*)&a[4] = *(float4*)&As[kk][64 + ty * 4];
            *(float4*)&b[0] = *(float4*)&Bs[kk][tx * 4];
            *(float4*)&b[4] = *(float4*)&Bs[kk][64 + tx * 4];
#pragma unroll
            for (int i = 0; i < 8; i++)
#pragma unroll
                for (int j = 0; j < 8; j++)
                    acc[i][j] += a[i] * b[j];
        }
        __syncthreads();
    }
#pragma unroll
    for (int i = 0; i < 8; i++) {
        int row = bm + ((i < 4) ? (ty * 4 + i) : (64 + ty * 4 + (i - 4)));
        float4 v0 = make_float4(acc[i][0], acc[i][1], acc[i][2], acc[i][3]);
        float4 v1 = make_float4(acc[i][4], acc[i][5], acc[i][6], acc[i][7]);
        *(float4*)&C[(size_t)row * N + bn + tx * 4] = v0;
        *(float4*)&C[(size_t)row * N + bn + 64 + tx * 4] = v1;
    }
}

// ---------------------------------------------------------------------------
// RoPE in-place on q (heads 0..31) and k (heads 32..39) inside g_qkv.
// ---------------------------------------------------------------------------
__global__ void rope_kernel(float* __restrict__ qkv,
                            const float* __restrict__ cosb,
                            const float* __restrict__ sinb)
{
    int idx = blockIdx.x * blockDim.x + threadIdx.x;
    const int total = BB * SS * (NQ + NKV) * 64;
    if (idx >= total) return;
    int d = idx & 63;
    int rest = idx >> 6;
    int hh = rest % (NQ + NKV);
    int s = (rest / (NQ + NKV)) % SS;
    int b = rest / ((NQ + NKV) * SS);
    float* base = &qkv[((size_t)(b * SS + s)) * QKVN + hh * DD];
    float x1 = base[d], x2 = base[d + 64];
    float c0 = cosb[s * DD + d],      s0 = sinb[s * DD + d];
    float c1 = cosb[s * DD + d + 64], s1 = sinb[s * DD + d + 64];
    base[d]      = x1 * c0 - x2 * s0;
    base[d + 64] = x2 * c1 + x1 * s1;
}

// ---------------------------------------------------------------------------
// Flash attention: one block = (64 queries, one q-head, one batch).
// Online softmax over key tiles of 64. Keys/values: cache for t<P, new
// (RoPE'd) k / new v from g_qkv for t>=P. Causal mask: t <= s + P.
// ---------------------------------------------------------------------------
#define FA_SMEM ((2 * 128 * 68 + 64 * 128 + 64 * 68 + 192) * 4)

__global__ __launch_bounds__(256) void flash_attn(
    const float* __restrict__ qkv,
    const float* __restrict__ kcache,
    const float* __restrict__ vcache,
    float* __restrict__ attn)
{
    extern __shared__ float sm[];
    float (*Qst)[68] = (float(*)[68])sm;                           // [128][68]
    float (*Kst)[68] = (float(*)[68])(sm + 128 * 68);              // [128][68]
    float (*Vs)[128] = (float(*)[128])(sm + 2 * 128 * 68);         // [64][128]
    float (*Ssm)[68] = (float(*)[68])(sm + 2 * 128 * 68 + 64 * 128); // [64][68]
    float* mrow = sm + 2 * 128 * 68 + 64 * 128 + 64 * 68;
    float* lrow = mrow + 64;
    float* resc = lrow + 64;

    const int tid = threadIdx.x;
    const int tx = tid & 15, ty = tid >> 4;
    const int sq0 = blockIdx.x * 64;
    const int h = blockIdx.y;
    const int b = blockIdx.z;
    const int kh = h >> 2;   // G = 4

    // Load Q tile transposed (k-major) and pre-scaled.
#pragma unroll
    for (int i = 0; i < 8; i++) {
        int id = tid + i * 256;            // 0..2047 (float4 ids)
        int row = id >> 5, d4 = (id & 31) << 2;
        float4 v = *(const float4*)&qkv[((size_t)(b * SS + sq0 + row)) * QKVN
                                        + h * DD + d4];
        Qst[d4 + 0][row] = v.x * SCALE;
        Qst[d4 + 1][row] = v.y * SCALE;
        Qst[d4 + 2][row] = v.z * SCALE;
        Qst[d4 + 3][row] = v.w * SCALE;
    }
    if (tid < 64) { mrow[tid] = -1e30f; lrow[tid] = 0.f; }

    float o[4][8];
#pragma unroll
    for (int i = 0; i < 4; i++)
#pragma unroll
        for (int j = 0; j < 8; j++) o[i][j] = 0.f;

    const int nt = (PP + sq0 + 64) / 64;   // key tiles to process
    for (int kt = 0; kt < nt; kt++) {
        const int kt0 = kt * 64;
        __syncthreads();   // prior PV done before overwriting K/V/S smem

        // Load K (transposed) and V tiles.
#pragma unroll
        for (int i = 0; i < 8; i++) {
            int id = tid + i * 256;
            int r = id >> 5, d4 = (id & 31) << 2;
            int t = kt0 + r;
            const float *ksrc, *vsrc;
            if (t < PP) {
                size_t base = (((size_t)(b * PP + t)) * NKV + kh) * DD + d4;
                ksrc = &kcache[base];
                vsrc = &vcache[base];
            } else {
                const float* base = &qkv[((size_t)(b * SS + (t - PP))) * QKVN];
                ksrc = base + (NQ + kh) * DD + d4;
                vsrc = base + (NQ + NKV + kh) * DD + d4;
            }
            float4 k4 = *(const float4*)ksrc;
            Kst[d4 + 0][r] = k4.x;
            Kst[d4 + 1][r] = k4.y;
            Kst[d4 + 2][r] = k4.z;
            Kst[d4 + 3][r] = k4.w;
            *(float4*)&Vs[r][d4] = *(const float4*)vsrc;
        }
        __syncthreads();

        // S = Q @ K^T  (64x64, 4x4 micro-tile per thread)
        float s4[4][4];
#pragma unroll
        for (int i = 0; i < 4; i++)
#pragma unroll
            for (int j = 0; j < 4; j++) s4[i][j] = 0.f;
#pragma unroll 4
        for (int d = 0; d < 128; d++) {
            float4 a = *(float4*)&Qst[d][ty * 4];
            float4 bb = *(float4*)&Kst[d][tx * 4];
            float av[4] = {a.x, a.y, a.z, a.w};
            float bv[4] = {bb.x, bb.y, bb.z, bb.w};
#pragma unroll
            for (int i = 0; i < 4; i++)
#pragma unroll
                for (int j = 0; j < 4; j++)
                    s4[i][j] += av[i] * bv[j];
        }
#pragma unroll
        for (int i = 0; i < 4; i++)
            *(float4*)&Ssm[ty * 4 + i][tx * 4] =
                make_float4(s4[i][0], s4[i][1], s4[i][2], s4[i][3]);
        __syncthreads();

        // Online softmax (one thread per row)
        if (tid < 64) {
            int row = tid;
            int tmax = sq0 + row + PP;
            int climit = tmax - kt0 + 1;
            if (climit > 64) climit = 64;
            float m_old = mrow[row];
            float mx = m_old;
            for (int c = 0; c < climit; c++) mx = fmaxf(mx, Ssm[row][c]);
            float sum = 0.f;
            for (int c = 0; c < 64; c++) {
                float p = (c < climit) ? __expf(Ssm[row][c] - mx) : 0.f;
                Ssm[row][c] = p;
                sum += p;
            }
            float rs = __expf(m_old - mx);
            lrow[row] = lrow[row] * rs + sum;
            mrow[row] = mx;
            resc[row] = rs;
        }
        __syncthreads();

        // Rescale O and accumulate P @ V
        float r[4];
#pragma unroll
        for (int i = 0; i < 4; i++) r[i] = resc[ty * 4 + i];
#pragma unroll
        for (int i = 0; i < 4; i++)
#pragma unroll
            for (int j = 0; j < 8; j++) o[i][j] *= r[i];

#pragma unroll 4
        for (int t = 0; t < 64; t++) {
            float p[4];
#pragma unroll
            for (int i = 0; i < 4; i++) p[i] = Ssm[ty * 4 + i][t];
            float4 v0 = *(float4*)&Vs[t][tx * 4];
            float4 v1 = *(float4*)&Vs[t][64 + tx * 4];
#pragma unroll
            for (int i = 0; i < 4; i++) {
                o[i][0] += p[i] * v0.x;
                o[i][1] += p[i] * v0.y;
                o[i][2] += p[i] * v0.z;
                o[i][3] += p[i] * v0.w;
                o[i][4] += p[i] * v1.x;
                o[i][5] += p[i] * v1.y;
                o[i][6] += p[i] * v1.z;
                o[i][7] += p[i] * v1.w;
            }
        }
    }

    // Epilogue: divide by l, write to attn scratch [B,S,NQ*D]
#pragma unroll
    for (int i = 0; i < 4; i++) {
        int row = ty * 4 + i;
        float inv = 1.f / lrow[row];
        size_t base = ((size_t)(b * SS + sq0 + row)) * (NQ * DD) + h * DD;
        float4 o0 = make_float4(o[i][0] * inv, o[i][1] * inv,
                                o[i][2] * inv, o[i][3] * inv);
        float4 o1 = make_float4(o[i][4] * inv, o[i][5] * inv,
                                o[i][6] * inv, o[i][7] * inv);
        *(float4*)&attn[base + tx * 4] = o0;
        *(float4*)&attn[base + 64 + tx * 4] = o1;
    }
}

// ---------------------------------------------------------------------------
extern "C" void kernel_launch(void* const* d_in, const int* in_sizes, int n_in,
                              void* d_out, int out_size)
{
    const float* hidden = (const float*)d_in[0];  // [B,S,H]
    const float* w_qkv  = (const float*)d_in[1];  // [H, 6144]
    const float* w_o    = (const float*)d_in[2];  // [4096, H]
    const float* cosb   = (const float*)d_in[3];  // [S, D]
    const float* sinb   = (const float*)d_in[4];  // [S, D]
    const float* kc     = (const float*)d_in[5];  // [B,P,NKV,D]
    const float* vc     = (const float*)d_in[6];  // [B,P,NKV,D]
    float* out = (float*)d_out;                   // [B,S,H]

    float *qkv, *attn;
    cudaGetSymbolAddress((void**)&qkv, g_qkv);
    cudaGetSymbolAddress((void**)&attn, g_attn);
    cudaFuncSetAttribute(flash_attn,
                         cudaFuncAttributeMaxDynamicSharedMemorySize, FA_SMEM);

    const int M = BB * SS;  // 2048

    // 1) QKV projection
    {
        dim3 grid(QKVN / 128, M / 128);
        sgemm128<<<grid, 256>>>(hidden, w_qkv, qkv, M, QKVN, HH);
    }
    // 2) RoPE on q and k
    {
        int total = BB * SS * (NQ + NKV) * 64;
        rope_kernel<<<(total + 255) / 256, 256>>>(qkv, cosb, sinb);
    }
    // 3) Flash attention
    {
        dim3 grid(SS / 64, NQ, BB);
        flash_attn<<<grid, 256, FA_SMEM>>>(qkv, kc, vc, attn);
    }
    // 4) Output projection
    {
        dim3 grid(HH / 128, M / 128);
        sgemm128<<<grid, 256>>>(attn, w_o, out, M, HH, HH);
    }
}

// round 3
// speedup vs baseline: 1.5835x; 1.5835x over previous
#include <cuda_runtime.h>
#include <cuda_bf16.h>
#include <math.h>
#include <stdint.h>

// Problem constants
#define BB   2
#define SS   1024
#define PP   1024
#define HH   4096
#define NQ   32
#define NKV  8
#define DD   128
#define QKVN ((NQ + 2 * NKV) * DD)   // 6144
#define SCALE 0.08838834764831845f   // 1/sqrt(128)

// ---------------------------------------------------------------------------
// Scratch (device globals: no allocation allowed)
// ---------------------------------------------------------------------------
__device__ float g_qkv[BB * SS * QKVN];                       // 50 MB fp32
__device__ __nv_bfloat16 g_hid_h[BB * SS * HH];
__device__ __nv_bfloat16 g_hid_l[BB * SS * HH];
__device__ __nv_bfloat16 g_wqkv_h[(size_t)QKVN * HH];         // transposed [N,K]
__device__ __nv_bfloat16 g_wqkv_l[(size_t)QKVN * HH];
__device__ __nv_bfloat16 g_wo_h[(size_t)HH * HH];             // transposed [N,K]
__device__ __nv_bfloat16 g_wo_l[(size_t)HH * HH];
__device__ __nv_bfloat16 g_attn_h[BB * SS * NQ * DD];
__device__ __nv_bfloat16 g_attn_l[BB * SS * NQ * DD];

// ---------------------------------------------------------------------------
// Low-level helpers (all plain sm_80+ ISA; no 'a'-suffix features)
// ---------------------------------------------------------------------------
__device__ __forceinline__ uint32_t smem_u32(const void* p) {
    uint32_t a;
    asm("{ .reg .u64 t; cvta.to.shared.u64 t, %1; cvt.u32.u64 %0, t; }"
        : "=r"(a) : "l"(p));
    return a;
}
__device__ __forceinline__ void cp16(uint32_t dst, const void* src) {
    asm volatile("cp.async.cg.shared.global [%0], [%1], 16;"
                 :: "r"(dst), "l"(src));
}
__device__ __forceinline__ void ldsm4(uint32_t* r, uint32_t a) {
    asm volatile("ldmatrix.sync.aligned.m8n8.x4.shared.b16 {%0,%1,%2,%3}, [%4];"
                 : "=r"(r[0]), "=r"(r[1]), "=r"(r[2]), "=r"(r[3]) : "r"(a));
}
__device__ __forceinline__ void mma16816(float* c, const uint32_t* a,
                                         const uint32_t b0, const uint32_t b1) {
    asm volatile(
        "mma.sync.aligned.m16n8k16.row.col.f32.bf16.bf16.f32 "
        "{%0,%1,%2,%3}, {%4,%5,%6,%7}, {%8,%9}, {%0,%1,%2,%3};"
        : "+f"(c[0]), "+f"(c[1]), "+f"(c[2]), "+f"(c[3])
        : "r"(a[0]), "r"(a[1]), "r"(a[2]), "r"(a[3]), "r"(b0), "r"(b1));
}

// ---------------------------------------------------------------------------
// fp32 -> bf16 hi/lo split (same layout)
// ---------------------------------------------------------------------------
__global__ void split_kernel(const float* __restrict__ x,
                             __nv_bfloat16* __restrict__ xh,
                             __nv_bfloat16* __restrict__ xl, int n)
{
    int i = blockIdx.x * blockDim.x + threadIdx.x;
    if (i >= n) return;
    float v = x[i];
    __nv_bfloat16 hb = __float2bfloat16(v);
    xh[i] = hb;
    xl[i] = __float2bfloat16(v - __bfloat162float(hb));
}

// fp32 [R,C] -> bf16 hi/lo transposed [C,R]
__global__ void split_t_kernel(const float* __restrict__ x,
                               __nv_bfloat16* __restrict__ xh,
                               __nv_bfloat16* __restrict__ xl, int R, int C)
{
    __shared__ float t[32][33];
    int r0 = blockIdx.y * 32, c0 = blockIdx.x * 32;
    int tx = threadIdx.x, ty = threadIdx.y;
#pragma unroll
    for (int j = 0; j < 4; j++)
        t[ty + 8 * j][tx] = x[(size_t)(r0 + ty + 8 * j) * C + c0 + tx];
    __syncthreads();
#pragma unroll
    for (int j = 0; j < 4; j++) {
        float v = t[tx][ty + 8 * j];
        __nv_bfloat16 hb = __float2bfloat16(v);
        size_t o = (size_t)(c0 + ty + 8 * j) * R + r0 + tx;
        xh[o] = hb;
        xl[o] = __float2bfloat16(v - __bfloat162float(hb));
    }
}

// ---------------------------------------------------------------------------
// bf16x3 GEMM via mma.sync: C[M,N] fp32 = (Ah+Al)[M,K] @ (Bh+Bl)[N,K]^T
// 128x128x64 tile, 8 warps (warp tile 64x32), cp.async double buffer,
// xor-swizzled smem rows (64 bf16 = 128B/row) for conflict-free ldmatrix.
// ---------------------------------------------------------------------------
#define TILE_B   16384            // one 128x64 bf16 tile
#define STAGE_B  (4 * TILE_B)     // Ah, Al, Bh, Bl
#define GEMM_SMEM (2 * STAGE_B)   // 131072

#define LOAD_STAGE(c, s) do {                                              \
    int _k0 = (c) * 64;                                                    \
    _Pragma("unroll")                                                      \
    for (int _m4 = 0; _m4 < 4; _m4++) {                                    \
        _Pragma("unroll")                                                  \
        for (int _i = 0; _i < 4; _i++) {                                   \
            int _id = tid + _i * 256;                                      \
            int _row = _id >> 3, _ch = _id & 7;                            \
            uint32_t _dst = smb + (s) * STAGE_B + _m4 * TILE_B             \
                          + (_row << 7) + ((_ch ^ (_row & 7)) << 4);       \
            cp16(_dst, srcs[_m4] + (size_t)_row * K + _k0 + _ch * 8);      \
        }                                                                  \
    }                                                                      \
    asm volatile("cp.async.commit_group;");                                \
} while (0)

__global__ __launch_bounds__(256, 1) void gemm_bf16x3(
    const __nv_bfloat16* __restrict__ Ah, const __nv_bfloat16* __restrict__ Al,
    const __nv_bfloat16* __restrict__ Bh, const __nv_bfloat16* __restrict__ Bl,
    float* __restrict__ C, int M, int N, int K)
{
    extern __shared__ char sm[];
    const uint32_t smb = smem_u32(sm);
    const int tid = threadIdx.x;
    const int wid = tid >> 5, lane = tid & 31;
    const int bm = blockIdx.y * 128, bn = blockIdx.x * 128;
    const int wm = (wid & 1) * 64, wn = (wid >> 1) * 32;

    const __nv_bfloat16* srcs[4] = {
        Ah + (size_t)bm * K, Al + (size_t)bm * K,
        Bh + (size_t)bn * K, Bl + (size_t)bn * K };

    float acc[16][4];
#pragma unroll
    for (int i = 0; i < 16; i++)
#pragma unroll
        for (int j = 0; j < 4; j++) acc[i][j] = 0.f;

    const int NC = K / 64;
    LOAD_STAGE(0, 0);

    for (int c = 0; c < NC; c++) {
        const int s = c & 1;
        if (c + 1 < NC) {
            LOAD_STAGE(c + 1, s ^ 1);
            asm volatile("cp.async.wait_group 1;");
        } else {
            asm volatile("cp.async.wait_group 0;");
        }
        __syncthreads();

        const uint32_t base = smb + s * STAGE_B;
#pragma unroll
        for (int ks = 0; ks < 4; ks++) {
            const int c0 = ks * 2 + (lane >> 4);   // 16B-chunk index for this lane
            uint32_t ah[4][4], al[4][4], bh[2][4], bl[2][4];
#pragma unroll
            for (int mi = 0; mi < 4; mi++) {
                int row = wm + mi * 16 + (lane & 15);
                uint32_t off = (row << 7) + ((c0 ^ (row & 7)) << 4);
                ldsm4(ah[mi], base + off);
                ldsm4(al[mi], base + TILE_B + off);
            }
#pragma unroll
            for (int ni = 0; ni < 2; ni++) {
                int row = wn + ni * 16 + (lane & 15);
                uint32_t off = (row << 7) + ((c0 ^ (row & 7)) << 4);
                ldsm4(bh[ni], base + 2 * TILE_B + off);
                ldsm4(bl[ni], base + 3 * TILE_B + off);
            }
#pragma unroll
            for (int mi = 0; mi < 4; mi++) {
#pragma unroll
                for (int nj = 0; nj < 4; nj++) {
                    const int ni = nj >> 1, sel = nj & 1;
                    float* a = acc[mi * 4 + nj];
                    mma16816(a, ah[mi], bh[ni][sel], bh[ni][sel + 2]);
                    mma16816(a, ah[mi], bl[ni][sel], bl[ni][sel + 2]);
                    mma16816(a, al[mi], bh[ni][sel], bh[ni][sel + 2]);
                }
            }
        }
        __syncthreads();
    }

    // Epilogue
    const int g = lane >> 2, t = lane & 3;
#pragma unroll
    for (int mi = 0; mi < 4; mi++) {
#pragma unroll
        for (int nj = 0; nj < 4; nj++) {
            const float* a = acc[mi * 4 + nj];
            int row = bm + wm + mi * 16 + g;
            int col = bn + wn + nj * 8 + t * 2;
            *(float2*)&C[(size_t)row * N + col] = make_float2(a[0], a[1]);
            *(float2*)&C[(size_t)(row + 8) * N + col] = make_float2(a[2], a[3]);
        }
    }
}

// ---------------------------------------------------------------------------
// RoPE in-place on q (heads 0..31) and k (heads 32..39) inside g_qkv.
// ---------------------------------------------------------------------------
__global__ void rope_kernel(float* __restrict__ qkv,
                            const float* __restrict__ cosb,
                            const float* __restrict__ sinb)
{
    int idx = blockIdx.x * blockDim.x + threadIdx.x;
    const int total = BB * SS * (NQ + NKV) * 64;
    if (idx >= total) return;
    int d = idx & 63;
    int rest = idx >> 6;
    int hh = rest % (NQ + NKV);
    int s = (rest / (NQ + NKV)) % SS;
    int b = rest / ((NQ + NKV) * SS);
    float* base = &qkv[((size_t)(b * SS + s)) * QKVN + hh * DD];
    float x1 = base[d], x2 = base[d + 64];
    float c0 = cosb[s * DD + d],      s0 = sinb[s * DD + d];
    float c1 = cosb[s * DD + d + 64], s1 = sinb[s * DD + d + 64];
    base[d]      = x1 * c0 - x2 * s0;
    base[d + 64] = x2 * c1 + x1 * s1;
}

// ---------------------------------------------------------------------------
// Flash attention (fp32), epilogue writes bf16 hi/lo for the output GEMM.
// ---------------------------------------------------------------------------
#define FA_SMEM ((2 * 128 * 68 + 64 * 128 + 64 * 68 + 192) * 4)

__global__ __launch_bounds__(256) void flash_attn(
    const float* __restrict__ qkv,
    const float* __restrict__ kcache,
    const float* __restrict__ vcache,
    __nv_bfloat16* __restrict__ attnh,
    __nv_bfloat16* __restrict__ attnl)
{
    extern __shared__ float smf[];
    float (*Qst)[68] = (float(*)[68])smf;
    float (*Kst)[68] = (float(*)[68])(smf + 128 * 68);
    float (*Vs)[128] = (float(*)[128])(smf + 2 * 128 * 68);
    float (*Ssm)[68] = (float(*)[68])(smf + 2 * 128 * 68 + 64 * 128);
    float* mrow = smf + 2 * 128 * 68 + 64 * 128 + 64 * 68;
    float* lrow = mrow + 64;
    float* resc = lrow + 64;

    const int tid = threadIdx.x;
    const int tx = tid & 15, ty = tid >> 4;
    const int sq0 = blockIdx.x * 64;
    const int h = blockIdx.y;
    const int b = blockIdx.z;
    const int kh = h >> 2;

#pragma unroll
    for (int i = 0; i < 8; i++) {
        int id = tid + i * 256;
        int row = id >> 5, d4 = (id & 31) << 2;
        float4 v = *(const float4*)&qkv[((size_t)(b * SS + sq0 + row)) * QKVN
                                        + h * DD + d4];
        Qst[d4 + 0][row] = v.x * SCALE;
        Qst[d4 + 1][row] = v.y * SCALE;
        Qst[d4 + 2][row] = v.z * SCALE;
        Qst[d4 + 3][row] = v.w * SCALE;
    }
    if (tid < 64) { mrow[tid] = -1e30f; lrow[tid] = 0.f; }

    float o[4][8];
#pragma unroll
    for (int i = 0; i < 4; i++)
#pragma unroll
        for (int j = 0; j < 8; j++) o[i][j] = 0.f;

    const int nt = (PP + sq0 + 64) / 64;
    for (int kt = 0; kt < nt; kt++) {
        const int kt0 = kt * 64;
        __syncthreads();
#pragma unroll
        for (int i = 0; i < 8; i++) {
            int id = tid + i * 256;
            int r = id >> 5, d4 = (id & 31) << 2;
            int t = kt0 + r;
            const float *ksrc, *vsrc;
            if (t < PP) {
                size_t base = (((size_t)(b * PP + t)) * NKV + kh) * DD + d4;
                ksrc = &kcache[base];
                vsrc = &vcache[base];
            } else {
                const float* base = &qkv[((size_t)(b * SS + (t - PP))) * QKVN];
                ksrc = base + (NQ + kh) * DD + d4;
                vsrc = base + (NQ + NKV + kh) * DD + d4;
            }
            float4 k4 = *(const float4*)ksrc;
            Kst[d4 + 0][r] = k4.x;
            Kst[d4 + 1][r] = k4.y;
            Kst[d4 + 2][r] = k4.z;
            Kst[d4 + 3][r] = k4.w;
            *(float4*)&Vs[r][d4] = *(const float4*)vsrc;
        }
        __syncthreads();

        float s4[4][4];
#pragma unroll
        for (int i = 0; i < 4; i++)
#pragma unroll
            for (int j = 0; j < 4; j++) s4[i][j] = 0.f;
#pragma unroll 4
        for (int d = 0; d < 128; d++) {
            float4 a = *(float4*)&Qst[d][ty * 4];
            float4 bb = *(float4*)&Kst[d][tx * 4];
            float av[4] = {a.x, a.y, a.z, a.w};
            float bv[4] = {bb.x, bb.y, bb.z, bb.w};
#pragma unroll
            for (int i = 0; i < 4; i++)
#pragma unroll
                for (int j = 0; j < 4; j++)
                    s4[i][j] += av[i] * bv[j];
        }
#pragma unroll
        for (int i = 0; i < 4; i++)
            *(float4*)&Ssm[ty * 4 + i][tx * 4] =
                make_float4(s4[i][0], s4[i][1], s4[i][2], s4[i][3]);
        __syncthreads();

        if (tid < 64) {
            int row = tid;
            int tmax = sq0 + row + PP;
            int climit = tmax - kt0 + 1;
            if (climit > 64) climit = 64;
            float m_old = mrow[row];
            float mx = m_old;
            for (int c = 0; c < climit; c++) mx = fmaxf(mx, Ssm[row][c]);
            float sum = 0.f;
            for (int c = 0; c < 64; c++) {
                float p = (c < climit) ? __expf(Ssm[row][c] - mx) : 0.f;
                Ssm[row][c] = p;
                sum += p;
            }
            float rs = __expf(m_old - mx);
            lrow[row] = lrow[row] * rs + sum;
            mrow[row] = mx;
            resc[row] = rs;
        }
        __syncthreads();

        float r[4];
#pragma unroll
        for (int i = 0; i < 4; i++) r[i] = resc[ty * 4 + i];
#pragma unroll
        for (int i = 0; i < 4; i++)
#pragma unroll
            for (int j = 0; j < 8; j++) o[i][j] *= r[i];

#pragma unroll 4
        for (int t = 0; t < 64; t++) {
            float p[4];
#pragma unroll
            for (int i = 0; i < 4; i++) p[i] = Ssm[ty * 4 + i][t];
            float4 v0 = *(float4*)&Vs[t][tx * 4];
            float4 v1 = *(float4*)&Vs[t][64 + tx * 4];
#pragma unroll
            for (int i = 0; i < 4; i++) {
                o[i][0] += p[i] * v0.x;
                o[i][1] += p[i] * v0.y;
                o[i][2] += p[i] * v0.z;
                o[i][3] += p[i] * v0.w;
                o[i][4] += p[i] * v1.x;
                o[i][5] += p[i] * v1.y;
                o[i][6] += p[i] * v1.z;
                o[i][7] += p[i] * v1.w;
            }
        }
    }

    // Epilogue: normalize, split to bf16 hi/lo, store for output GEMM
#pragma unroll
    for (int i = 0; i < 4; i++) {
        int row = ty * 4 + i;
        float inv = 1.f / lrow[row];
        size_t base = ((size_t)(b * SS + sq0 + row)) * (NQ * DD) + h * DD;
#pragma unroll
        for (int gg = 0; gg < 2; gg++) {
            __nv_bfloat16 hv[4], lv[4];
#pragma unroll
            for (int j = 0; j < 4; j++) {
                float v = o[i][gg * 4 + j] * inv;
                hv[j] = __float2bfloat16(v);
                lv[j] = __float2bfloat16(v - __bfloat162float(hv[j]));
            }
            size_t off = base + gg * 64 + tx * 4;
            *(__nv_bfloat162*)&attnh[off]     = __halves2bfloat162(hv[0], hv[1]);
            *(__nv_bfloat162*)&attnh[off + 2] = __halves2bfloat162(hv[2], hv[3]);
            *(__nv_bfloat162*)&attnl[off]     = __halves2bfloat162(lv[0], lv[1]);
            *(__nv_bfloat162*)&attnl[off + 2] = __halves2bfloat162(lv[2], lv[3]);
        }
    }
}

// ---------------------------------------------------------------------------
extern "C" void kernel_launch(void* const* d_in, const int* in_sizes, int n_in,
                              void* d_out, int out_size)
{
    const float* hidden = (const float*)d_in[0];
    const float* w_qkv  = (const float*)d_in[1];
    const float* w_o    = (const float*)d_in[2];
    const float* cosb   = (const float*)d_in[3];
    const float* sinb   = (const float*)d_in[4];
    const float* kc     = (const float*)d_in[5];
    const float* vc     = (const float*)d_in[6];
    float* out = (float*)d_out;

    float *qkv;
    __nv_bfloat16 *hidh, *hidl, *wqh, *wql, *woh, *wol, *ath, *atl;
    cudaGetSymbolAddress((void**)&qkv, g_qkv);
    cudaGetSymbolAddress((void**)&hidh, g_hid_h);
    cudaGetSymbolAddress((void**)&hidl, g_hid_l);
    cudaGetSymbolAddress((void**)&wqh, g_wqkv_h);
    cudaGetSymbolAddress((void**)&wql, g_wqkv_l);
    cudaGetSymbolAddress((void**)&woh, g_wo_h);
    cudaGetSymbolAddress((void**)&wol, g_wo_l);
    cudaGetSymbolAddress((void**)&ath, g_attn_h);
    cudaGetSymbolAddress((void**)&atl, g_attn_l);

    cudaFuncSetAttribute(gemm_bf16x3,
                         cudaFuncAttributeMaxDynamicSharedMemorySize, GEMM_SMEM);
    cudaFuncSetAttribute(flash_attn,
                         cudaFuncAttributeMaxDynamicSharedMemorySize, FA_SMEM);

    const int M = BB * SS;  // 2048

    // 0) hi/lo splits (+ weight transposes to [N,K])
    {
        int n = M * HH;
        split_kernel<<<(n + 255) / 256, 256>>>(hidden, hidh, hidl, n);
        split_t_kernel<<<dim3(QKVN / 32, HH / 32), dim3(32, 8)>>>(
            w_qkv, wqh, wql, HH, QKVN);
        split_t_kernel<<<dim3(HH / 32, HH / 32), dim3(32, 8)>>>(
            w_o, woh, wol, HH, HH);
    }
    // 1) QKV projection (bf16x3 tensor-core)
    gemm_bf16x3<<<dim3(QKVN / 128, M / 128), 256, GEMM_SMEM>>>(
        hidh, hidl, wqh, wql, qkv, M, QKVN, HH);
    // 2) RoPE on q and k
    {
        int total = BB * SS * (NQ + NKV) * 64;
        rope_kernel<<<(total + 255) / 256, 256>>>(qkv, cosb, sinb);
    }
    // 3) Flash attention (writes bf16 hi/lo activations)
    flash_attn<<<dim3(SS / 64, NQ, BB), 256, FA_SMEM>>>(qkv, kc, vc, ath, atl);
    // 4) Output projection (bf16x3 tensor-core)
    gemm_bf16x3<<<dim3(HH / 128, M / 128), 256, GEMM_SMEM>>>(
        ath, atl, woh, wol, out, M, HH, HH);
}

// round 4
// speedup vs baseline: 2.9708x; 1.8760x over previous
#include <cuda_runtime.h>
#include <cuda_bf16.h>
#include <math.h>
#include <stdint.h>

// Problem constants
#define BB   2
#define SS   1024
#define PP   1024
#define TT   (PP + SS)
#define HH   4096
#define NQ   32
#define NKV  8
#define DD   128
#define QKVN ((NQ + 2 * NKV) * DD)   // 6144
#define SCALE 0.08838834764831845f   // 1/sqrt(128)

// ---------------------------------------------------------------------------
// Scratch (device globals: no allocation allowed)
// ---------------------------------------------------------------------------
__device__ float g_qkv[BB * SS * QKVN];
__device__ __nv_bfloat16 g_hid_h[BB * SS * HH];
__device__ __nv_bfloat16 g_hid_l[BB * SS * HH];
__device__ __nv_bfloat16 g_wqkv_h[(size_t)QKVN * HH];   // transposed [N,K]
__device__ __nv_bfloat16 g_wqkv_l[(size_t)QKVN * HH];
__device__ __nv_bfloat16 g_wo_h[(size_t)HH * HH];       // transposed [N,K]
__device__ __nv_bfloat16 g_wo_l[(size_t)HH * HH];
__device__ __nv_bfloat16 g_attn_h[BB * SS * NQ * DD];
__device__ __nv_bfloat16 g_attn_l[BB * SS * NQ * DD];
// Q hi/lo [B][NQ][S][D]
__device__ __nv_bfloat16 g_q_h[(size_t)BB * NQ * SS * DD];
__device__ __nv_bfloat16 g_q_l[(size_t)BB * NQ * SS * DD];
// unified KV hi/lo [B][NKV][T][D]
__device__ __nv_bfloat16 g_k_h[(size_t)BB * NKV * TT * DD];
__device__ __nv_bfloat16 g_k_l[(size_t)BB * NKV * TT * DD];
__device__ __nv_bfloat16 g_v_h[(size_t)BB * NKV * TT * DD];
__device__ __nv_bfloat16 g_v_l[(size_t)BB * NKV * TT * DD];

// ---------------------------------------------------------------------------
// Low-level helpers (plain sm_80+ ISA)
// ---------------------------------------------------------------------------
__device__ __forceinline__ uint32_t smem_u32(const void* p) {
    uint32_t a;
    asm("{ .reg .u64 t; cvta.to.shared.u64 t, %1; cvt.u32.u64 %0, t; }"
        : "=r"(a) : "l"(p));
    return a;
}
__device__ __forceinline__ void cp16(uint32_t dst, const void* src) {
    asm volatile("cp.async.cg.shared.global [%0], [%1], 16;"
                 :: "r"(dst), "l"(src));
}
__device__ __forceinline__ void ldsm4(uint32_t* r, uint32_t a) {
    asm volatile("ldmatrix.sync.aligned.m8n8.x4.shared.b16 {%0,%1,%2,%3}, [%4];"
                 : "=r"(r[0]), "=r"(r[1]), "=r"(r[2]), "=r"(r[3]) : "r"(a));
}
__device__ __forceinline__ void ldsm4t(uint32_t* r, uint32_t a) {
    asm volatile("ldmatrix.sync.aligned.m8n8.x4.trans.shared.b16 {%0,%1,%2,%3}, [%4];"
                 : "=r"(r[0]), "=r"(r[1]), "=r"(r[2]), "=r"(r[3]) : "r"(a));
}
__device__ __forceinline__ void mma16816(float* c, const uint32_t* a,
                                         const uint32_t b0, const uint32_t b1) {
    asm volatile(
        "mma.sync.aligned.m16n8k16.row.col.f32.bf16.bf16.f32 "
        "{%0,%1,%2,%3}, {%4,%5,%6,%7}, {%8,%9}, {%0,%1,%2,%3};"
        : "+f"(c[0]), "+f"(c[1]), "+f"(c[2]), "+f"(c[3])
        : "r"(a[0]), "r"(a[1]), "r"(a[2]), "r"(a[3]), "r"(b0), "r"(b1));
}

// ---------------------------------------------------------------------------
// fp32 -> bf16 hi/lo split (same layout)
// ---------------------------------------------------------------------------
__global__ void split_kernel(const float* __restrict__ x,
                             __nv_bfloat16* __restrict__ xh,
                             __nv_bfloat16* __restrict__ xl, int n)
{
    int i = blockIdx.x * blockDim.x + threadIdx.x;
    if (i >= n) return;
    float v = x[i];
    __nv_bfloat16 hb = __float2bfloat16(v);
    xh[i] = hb;
    xl[i] = __float2bfloat16(v - __bfloat162float(hb));
}

// fp32 [R,C] -> bf16 hi/lo transposed [C,R]
__global__ void split_t_kernel(const float* __restrict__ x,
                               __nv_bfloat16* __restrict__ xh,
                               __nv_bfloat16* __restrict__ xl, int R, int C)
{
    __shared__ float t[32][33];
    int r0 = blockIdx.y * 32, c0 = blockIdx.x * 32;
    int tx = threadIdx.x, ty = threadIdx.y;
#pragma unroll
    for (int j = 0; j < 4; j++)
        t[ty + 8 * j][tx] = x[(size_t)(r0 + ty + 8 * j) * C + c0 + tx];
    __syncthreads();
#pragma unroll
    for (int j = 0; j < 4; j++) {
        float v = t[tx][ty + 8 * j];
        __nv_bfloat16 hb = __float2bfloat16(v);
        size_t o = (size_t)(c0 + ty + 8 * j) * R + r0 + tx;
        xh[o] = hb;
        xl[o] = __float2bfloat16(v - __bfloat162float(hb));
    }
}

// ---------------------------------------------------------------------------
// bf16x3 GEMM via mma.sync (unchanged from round 3)
// ---------------------------------------------------------------------------
#define TILE_B   16384
#define STAGE_B  (4 * TILE_B)
#define GEMM_SMEM (2 * STAGE_B)

#define LOAD_STAGE(c, s) do {                                              \
    int _k0 = (c) * 64;                                                    \
    _Pragma("unroll")                                                      \
    for (int _m4 = 0; _m4 < 4; _m4++) {                                    \
        _Pragma("unroll")                                                  \
        for (int _i = 0; _i < 4; _i++) {                                   \
            int _id = tid + _i * 256;                                      \
            int _row = _id >> 3, _ch = _id & 7;                            \
            uint32_t _dst = smb + (s) * STAGE_B + _m4 * TILE_B             \
                          + (_row << 7) + ((_ch ^ (_row & 7)) << 4);       \
            cp16(_dst, srcs[_m4] + (size_t)_row * K + _k0 + _ch * 8);      \
        }                                                                  \
    }                                                                      \
    asm volatile("cp.async.commit_group;");                                \
} while (0)

__global__ __launch_bounds__(256, 1) void gemm_bf16x3(
    const __nv_bfloat16* __restrict__ Ah, const __nv_bfloat16* __restrict__ Al,
    const __nv_bfloat16* __restrict__ Bh, const __nv_bfloat16* __restrict__ Bl,
    float* __restrict__ C, int M, int N, int K)
{
    extern __shared__ char sm[];
    const uint32_t smb = smem_u32(sm);
    const int tid = threadIdx.x;
    const int wid = tid >> 5, lane = tid & 31;
    const int bm = blockIdx.y * 128, bn = blockIdx.x * 128;
    const int wm = (wid & 1) * 64, wn = (wid >> 1) * 32;

    const __nv_bfloat16* srcs[4] = {
        Ah + (size_t)bm * K, Al + (size_t)bm * K,
        Bh + (size_t)bn * K, Bl + (size_t)bn * K };

    float acc[16][4];
#pragma unroll
    for (int i = 0; i < 16; i++)
#pragma unroll
        for (int j = 0; j < 4; j++) acc[i][j] = 0.f;

    const int NC = K / 64;
    LOAD_STAGE(0, 0);

    for (int c = 0; c < NC; c++) {
        const int s = c & 1;
        if (c + 1 < NC) {
            LOAD_STAGE(c + 1, s ^ 1);
            asm volatile("cp.async.wait_group 1;");
        } else {
            asm volatile("cp.async.wait_group 0;");
        }
        __syncthreads();

        const uint32_t base = smb + s * STAGE_B;
#pragma unroll
        for (int ks = 0; ks < 4; ks++) {
            const int c0 = ks * 2 + (lane >> 4);
            uint32_t ah[4][4], al[4][4], bh[2][4], bl[2][4];
#pragma unroll
            for (int mi = 0; mi < 4; mi++) {
                int row = wm + mi * 16 + (lane & 15);
                uint32_t off = (row << 7) + ((c0 ^ (row & 7)) << 4);
                ldsm4(ah[mi], base + off);
                ldsm4(al[mi], base + TILE_B + off);
            }
#pragma unroll
            for (int ni = 0; ni < 2; ni++) {
                int row = wn + ni * 16 + (lane & 15);
                uint32_t off = (row << 7) + ((c0 ^ (row & 7)) << 4);
                ldsm4(bh[ni], base + 2 * TILE_B + off);
                ldsm4(bl[ni], base + 3 * TILE_B + off);
            }
#pragma unroll
            for (int mi = 0; mi < 4; mi++) {
#pragma unroll
                for (int nj = 0; nj < 4; nj++) {
                    const int ni = nj >> 1, sel = nj & 1;
                    float* a = acc[mi * 4 + nj];
                    mma16816(a, ah[mi], bh[ni][sel], bh[ni][sel + 2]);
                    mma16816(a, ah[mi], bl[ni][sel], bl[ni][sel + 2]);
                    mma16816(a, al[mi], bh[ni][sel], bh[ni][sel + 2]);
                }
            }
        }
        __syncthreads();
    }

    const int g = lane >> 2, t = lane & 3;
#pragma unroll
    for (int mi = 0; mi < 4; mi++) {
#pragma unroll
        for (int nj = 0; nj < 4; nj++) {
            const float* a = acc[mi * 4 + nj];
            int row = bm + wm + mi * 16 + g;
            int col = bn + wn + nj * 8 + t * 2;
            *(float2*)&C[(size_t)row * N + col] = make_float2(a[0], a[1]);
            *(float2*)&C[(size_t)(row + 8) * N + col] = make_float2(a[2], a[3]);
        }
    }
}

// ---------------------------------------------------------------------------
// Pre-pass 1: RoPE + scale + hi/lo split of Q -> [B][NQ][S][D]
// ---------------------------------------------------------------------------
__global__ void rope_split_q(const float* __restrict__ qkv,
                             const float* __restrict__ cosb,
                             const float* __restrict__ sinb,
                             __nv_bfloat16* __restrict__ qh,
                             __nv_bfloat16* __restrict__ ql)
{
    int idx = blockIdx.x * blockDim.x + threadIdx.x;
    const int total = BB * SS * NQ * 64;
    if (idx >= total) return;
    int d = idx & 63;
    int rest = idx >> 6;
    int h = rest % NQ;
    int s = (rest / NQ) % SS;
    int b = rest / (NQ * SS);
    const float* base = &qkv[((size_t)(b * SS + s)) * QKVN + h * DD];
    float x1 = base[d], x2 = base[d + 64];
    float c0 = cosb[s * DD + d],      s0 = sinb[s * DD + d];
    float c1 = cosb[s * DD + d + 64], s1 = sinb[s * DD + d + 64];
    float y1 = (x1 * c0 - x2 * s0) * SCALE;
    float y2 = (x2 * c1 + x1 * s1) * SCALE;
    size_t o = (((size_t)(b * NQ + h)) * SS + s) * DD + d;
    __nv_bfloat16 h1 = __float2bfloat16(y1);
    __nv_bfloat16 h2 = __float2bfloat16(y2);
    qh[o] = h1;       qh[o + 64] = h2;
    ql[o] = __float2bfloat16(y1 - __bfloat162float(h1));
    ql[o + 64] = __float2bfloat16(y2 - __bfloat162float(h2));
}

// ---------------------------------------------------------------------------
// Pre-pass 2: unified KV hi/lo [B][NKV][T][D]; RoPE on new K rows.
// One thread handles one (b,kh,t, d in 0..63): elems d and d+64.
// ---------------------------------------------------------------------------
__global__ void build_kv(const float* __restrict__ qkv,
                         const float* __restrict__ kcache,
                         const float* __restrict__ vcache,
                         const float* __restrict__ cosb,
                         const float* __restrict__ sinb,
                         __nv_bfloat16* __restrict__ khp, __nv_bfloat16* __restrict__ klp,
                         __nv_bfloat16* __restrict__ vhp, __nv_bfloat16* __restrict__ vlp)
{
    int idx = blockIdx.x * blockDim.x + threadIdx.x;
    const int total = BB * NKV * TT * 64;
    if (idx >= total) return;
    int d = idx & 63;
    int rest = idx >> 6;
    int t = rest % TT;
    int kh = (rest / TT) % NKV;
    int b = rest / (TT * NKV);

    float k1, k2, v1, v2;
    if (t < PP) {
        size_t src = (((size_t)(b * PP + t)) * NKV + kh) * DD;
        k1 = kcache[src + d]; k2 = kcache[src + d + 64];
        v1 = vcache[src + d]; v2 = vcache[src + d + 64];
    } else {
        int s = t - PP;
        const float* base = &qkv[((size_t)(b * SS + s)) * QKVN];
        float x1 = base[(NQ + kh) * DD + d], x2 = base[(NQ + kh) * DD + d + 64];
        float c0 = cosb[s * DD + d],      s0 = sinb[s * DD + d];
        float c1 = cosb[s * DD + d + 64], s1 = sinb[s * DD + d + 64];
        k1 = x1 * c0 - x2 * s0;
        k2 = x2 * c1 + x1 * s1;
        v1 = base[(NQ + NKV + kh) * DD + d];
        v2 = base[(NQ + NKV + kh) * DD + d + 64];
    }
    size_t o = (((size_t)(b * NKV + kh)) * TT + t) * DD + d;
    __nv_bfloat16 a;
    a = __float2bfloat16(k1); khp[o] = a;      klp[o] = __float2bfloat16(k1 - __bfloat162float(a));
    a = __float2bfloat16(k2); khp[o + 64] = a; klp[o + 64] = __float2bfloat16(k2 - __bfloat162float(a));
    a = __float2bfloat16(v1); vhp[o] = a;      vlp[o] = __float2bfloat16(v1 - __bfloat162float(a));
    a = __float2bfloat16(v2); vhp[o + 64] = a; vlp[o + 64] = __float2bfloat16(v2 - __bfloat162float(a));
}

// ---------------------------------------------------------------------------
// Flash attention on tensor cores, bf16x3 for QK and PV.
// Block: 64 queries x (1 q-head) x (1 batch), 4 warps (16 q rows each).
// Key tiles of 64; K/V hi/lo in swizzled smem (64 rows x 256B).
// ---------------------------------------------------------------------------
#define FA_SMEM (4 * 64 * 256)   // 65536

__global__ __launch_bounds__(128) void flash_mma(
    const __nv_bfloat16* __restrict__ qh_g, const __nv_bfloat16* __restrict__ ql_g,
    const __nv_bfloat16* __restrict__ kh_g, const __nv_bfloat16* __restrict__ kl_g,
    const __nv_bfloat16* __restrict__ vh_g, const __nv_bfloat16* __restrict__ vl_g,
    __nv_bfloat16* __restrict__ attnh, __nv_bfloat16* __restrict__ attnl)
{
    extern __shared__ char sm[];
    const uint32_t smb = smem_u32(sm);
    const uint32_t KHO = 0, KLO = 16384, VHO = 32768, VLO = 49152;
    const int tid = threadIdx.x, lane = tid & 31, w = tid >> 5;
    const int qi = blockIdx.x, h = blockIdx.y, b = blockIdx.z;
    const int sq0 = qi * 64;
    const int khd = h >> 2;                // GQA: G=4
    const int g = lane >> 2, t4 = lane & 3;
    const int r0 = w * 16 + g, r1 = r0 + 8;   // local q rows

    // --- Q fragments straight from gmem (reused across all key tiles) ---
    uint32_t qfh[8][4], qfl[8][4];
    {
        const __nv_bfloat16* qbh = qh_g + (((size_t)(b * NQ + h)) * SS + sq0) * DD;
        const __nv_bfloat16* qbl = ql_g + (((size_t)(b * NQ + h)) * SS + sq0) * DD;
#pragma unroll
        for (int ks = 0; ks < 8; ks++) {
            int c0 = ks * 16 + 2 * t4;
            qfh[ks][0] = *(const uint32_t*)(qbh + r0 * DD + c0);
            qfh[ks][1] = *(const uint32_t*)(qbh + r1 * DD + c0);
            qfh[ks][2] = *(const uint32_t*)(qbh + r0 * DD + c0 + 8);
            qfh[ks][3] = *(const uint32_t*)(qbh + r1 * DD + c0 + 8);
            qfl[ks][0] = *(const uint32_t*)(qbl + r0 * DD + c0);
            qfl[ks][1] = *(const uint32_t*)(qbl + r1 * DD + c0);
            qfl[ks][2] = *(const uint32_t*)(qbl + r0 * DD + c0 + 8);
            qfl[ks][3] = *(const uint32_t*)(qbl + r1 * DD + c0 + 8);
        }
    }

    float oacc[16][4];
#pragma unroll
    for (int i = 0; i < 16; i++)
#pragma unroll
        for (int j = 0; j < 4; j++) oacc[i][j] = 0.f;
    float m0 = -1e30f, m1 = -1e30f, l0 = 0.f, l1 = 0.f;

    const size_t kvb = ((size_t)(b * NKV + khd)) * TT * DD;
    const int nt = qi + 1 + PP / 64;     // qi + 17

    for (int kt = 0; kt < nt; kt++) {
        __syncthreads();   // previous PV reads done
        // --- load K/V hi/lo tile (64 keys x 128 d) ---
        {
            const __nv_bfloat16* srcs[4] = {
                kh_g + kvb + (size_t)kt * 64 * DD,
                kl_g + kvb + (size_t)kt * 64 * DD,
                vh_g + kvb + (size_t)kt * 64 * DD,
                vl_g + kvb + (size_t)kt * 64 * DD };
            const uint32_t offs[4] = { KHO, KLO, VHO, VLO };
#pragma unroll
            for (int a = 0; a < 4; a++) {
#pragma unroll
                for (int i = 0; i < 8; i++) {
                    int id = tid + i * 128;
                    int r = id >> 4, ch = id & 15;
                    cp16(smb + offs[a] + r * 256 + ((ch ^ (r & 7)) << 4),
                         srcs[a] + r * DD + ch * 8);
                }
            }
            asm volatile("cp.async.commit_group;");
            asm volatile("cp.async.wait_group 0;");
            __syncthreads();
        }

        // --- S = Q K^T (bf16x3) ---
        float sacc[8][4];
#pragma unroll
        for (int j = 0; j < 8; j++)
#pragma unroll
            for (int e = 0; e < 4; e++) sacc[j][e] = 0.f;
#pragma unroll
        for (int ks = 0; ks < 8; ks++) {
            const int c0 = ks * 2 + (lane >> 4);
#pragma unroll
            for (int kg = 0; kg < 4; kg++) {
                int r = kg * 16 + (lane & 15);
                uint32_t off = r * 256 + ((c0 ^ (r & 7)) << 4);
                uint32_t kbh[4], kbl[4];
                ldsm4(kbh, smb + KHO + off);
                ldsm4(kbl, smb + KLO + off);
#pragma unroll
                for (int sel = 0; sel < 2; sel++) {
                    float* sj = sacc[kg * 2 + sel];
                    mma16816(sj, qfh[ks], kbh[sel], kbh[sel + 2]);
                    mma16816(sj, qfh[ks], kbl[sel], kbl[sel + 2]);
                    mma16816(sj, qfl[ks], kbh[sel], kbh[sel + 2]);
                }
            }
        }

        // --- causal mask (only last tile is diagonal) ---
        if (kt == nt - 1) {
#pragma unroll
            for (int j = 0; j < 8; j++) {
                int cb = j * 8 + 2 * t4;
                if (cb     > r0) sacc[j][0] = -1e30f;
                if (cb + 1 > r0) sacc[j][1] = -1e30f;
                if (cb     > r1) sacc[j][2] = -1e30f;
                if (cb + 1 > r1) sacc[j][3] = -1e30f;
            }
        }

        // --- online softmax ---
        float mx0 = m0, mx1 = m1;
#pragma unroll
        for (int j = 0; j < 8; j++) {
            mx0 = fmaxf(mx0, fmaxf(sacc[j][0], sacc[j][1]));
            mx1 = fmaxf(mx1, fmaxf(sacc[j][2], sacc[j][3]));
        }
        mx0 = fmaxf(mx0, __shfl_xor_sync(0xffffffff, mx0, 1));
        mx0 = fmaxf(mx0, __shfl_xor_sync(0xffffffff, mx0, 2));
        mx1 = fmaxf(mx1, __shfl_xor_sync(0xffffffff, mx1, 1));
        mx1 = fmaxf(mx1, __shfl_xor_sync(0xffffffff, mx1, 2));
        float rs0 = __expf(m0 - mx0), rs1 = __expf(m1 - mx1);
        m0 = mx0; m1 = mx1;
        l0 *= rs0; l1 *= rs1;

        uint32_t pfh[4][4], pfl[4][4];
#pragma unroll
        for (int j = 0; j < 8; j++) {
            float p0 = __expf(sacc[j][0] - m0);
            float p1 = __expf(sacc[j][1] - m0);
            float p2 = __expf(sacc[j][2] - m1);
            float p3 = __expf(sacc[j][3] - m1);
            l0 += p0 + p1; l1 += p2 + p3;
            int kk = j >> 1, u = (j & 1) * 2;
            __nv_bfloat162 hA = __float22bfloat162_rn(make_float2(p0, p1));
            float2 bA = __bfloat1622float2(hA);
            __nv_bfloat162 lA = __float22bfloat162_rn(make_float2(p0 - bA.x, p1 - bA.y));
            __nv_bfloat162 hB = __float22bfloat162_rn(make_float2(p2, p3));
            float2 bB = __bfloat1622float2(hB);
            __nv_bfloat162 lB = __float22bfloat162_rn(make_float2(p2 - bB.x, p3 - bB.y));
            pfh[kk][u]     = *(uint32_t*)&hA;
            pfh[kk][u + 1] = *(uint32_t*)&hB;
            pfl[kk][u]     = *(uint32_t*)&lA;
            pfl[kk][u + 1] = *(uint32_t*)&lB;
        }
        // NOTE: a-frag order is {rowg k0-7, rowg+8 k0-7, rowg k8-15, rowg+8 k8-15}
        // u mapping above places (j even -> regs 0,1) (j odd -> regs 2,3): fix order:
        // regs must be [0]=rowg/klo, [1]=rowg+8/klo, [2]=rowg/khi, [3]=rowg+8/khi.
        // With u = (j&1)*2: j even -> pfh[kk][0]=rowg, [1]=rowg+8 (k-half 0);
        //                   j odd  -> pfh[kk][2]=rowg, [3]=rowg+8 (k-half 1).  Correct.

        // --- rescale O ---
#pragma unroll
        for (int i = 0; i < 16; i++) {
            oacc[i][0] *= rs0; oacc[i][1] *= rs0;
            oacc[i][2] *= rs1; oacc[i][3] *= rs1;
        }

        // --- O += P V (bf16x3) ---
#pragma unroll
        for (int kk = 0; kk < 4; kk++) {
#pragma unroll
            for (int dg = 0; dg < 8; dg++) {
                int r = kk * 16 + (lane & 15);
                int c0 = dg * 2 + (lane >> 4);
                uint32_t off = r * 256 + ((c0 ^ (r & 7)) << 4);
                uint32_t vbh[4], vbl[4];
                ldsm4t(vbh, smb + VHO + off);
                ldsm4t(vbl, smb + VLO + off);
                float* oA = oacc[dg * 2];
                float* oB = oacc[dg * 2 + 1];
                mma16816(oA, pfh[kk], vbh[0], vbh[1]);
                mma16816(oA, pfh[kk], vbl[0], vbl[1]);
                mma16816(oA, pfl[kk], vbh[0], vbh[1]);
                mma16816(oB, pfh[kk], vbh[2], vbh[3]);
                mma16816(oB, pfh[kk], vbl[2], vbl[3]);
                mma16816(oB, pfl[kk], vbh[2], vbh[3]);
            }
        }
    }

    // --- epilogue: finish l, normalize, split hi/lo, store ---
    l0 += __shfl_xor_sync(0xffffffff, l0, 1);
    l0 += __shfl_xor_sync(0xffffffff, l0, 2);
    l1 += __shfl_xor_sync(0xffffffff, l1, 1);
    l1 += __shfl_xor_sync(0xffffffff, l1, 2);
    float inv0 = 1.f / l0, inv1 = 1.f / l1;

    size_t rowA = ((size_t)(b * SS + sq0 + r0)) * (NQ * DD) + h * DD;
    size_t rowB = ((size_t)(b * SS + sq0 + r1)) * (NQ * DD) + h * DD;
#pragma unroll
    for (int dt = 0; dt < 16; dt++) {
        int c = dt * 8 + 2 * t4;
        float v0 = oacc[dt][0] * inv0, v1 = oacc[dt][1] * inv0;
        float v2 = oacc[dt][2] * inv1, v3 = oacc[dt][3] * inv1;
        __nv_bfloat162 hA = __float22bfloat162_rn(make_float2(v0, v1));
        float2 bA = __bfloat1622float2(hA);
        __nv_bfloat162 lA = __float22bfloat162_rn(make_float2(v0 - bA.x, v1 - bA.y));
        __nv_bfloat162 hB = __float22bfloat162_rn(make_float2(v2, v3));
        float2 bB = __bfloat1622float2(hB);
        __nv_bfloat162 lB = __float22bfloat162_rn(make_float2(v2 - bB.x, v3 - bB.y));
        *(__nv_bfloat162*)&attnh[rowA + c] = hA;
        *(__nv_bfloat162*)&attnl[rowA + c] = lA;
        *(__nv_bfloat162*)&attnh[rowB + c] = hB;
        *(__nv_bfloat162*)&attnl[rowB + c] = lB;
    }
}

// ---------------------------------------------------------------------------
extern "C" void kernel_launch(void* const* d_in, const int* in_sizes, int n_in,
                              void* d_out, int out_size)
{
    const float* hidden = (const float*)d_in[0];
    const float* w_qkv  = (const float*)d_in[1];
    const float* w_o    = (const float*)d_in[2];
    const float* cosb   = (const float*)d_in[3];
    const float* sinb   = (const float*)d_in[4];
    const float* kc     = (const float*)d_in[5];
    const float* vc     = (const float*)d_in[6];
    float* out = (float*)d_out;

    float *qkv;
    __nv_bfloat16 *hidh, *hidl, *wqh, *wql, *woh, *wol, *ath, *atl;
    __nv_bfloat16 *qh, *ql, *kh, *kl, *vh, *vl;
    cudaGetSymbolAddress((void**)&qkv, g_qkv);
    cudaGetSymbolAddress((void**)&hidh, g_hid_h);
    cudaGetSymbolAddress((void**)&hidl, g_hid_l);
    cudaGetSymbolAddress((void**)&wqh, g_wqkv_h);
    cudaGetSymbolAddress((void**)&wql, g_wqkv_l);
    cudaGetSymbolAddress((void**)&woh, g_wo_h);
    cudaGetSymbolAddress((void**)&wol, g_wo_l);
    cudaGetSymbolAddress((void**)&ath, g_attn_h);
    cudaGetSymbolAddress((void**)&atl, g_attn_l);
    cudaGetSymbolAddress((void**)&qh, g_q_h);
    cudaGetSymbolAddress((void**)&ql, g_q_l);
    cudaGetSymbolAddress((void**)&kh, g_k_h);
    cudaGetSymbolAddress((void**)&kl, g_k_l);
    cudaGetSymbolAddress((void**)&vh, g_v_h);
    cudaGetSymbolAddress((void**)&vl, g_v_l);

    cudaFuncSetAttribute(gemm_bf16x3,
                         cudaFuncAttributeMaxDynamicSharedMemorySize, GEMM_SMEM);
    cudaFuncSetAttribute(flash_mma,
                         cudaFuncAttributeMaxDynamicSharedMemorySize, FA_SMEM);

    const int M = BB * SS;  // 2048

    // 0) hi/lo splits (+ weight transposes to [N,K])
    {
        int n = M * HH;
        split_kernel<<<(n + 255) / 256, 256>>>(hidden, hidh, hidl, n);
        split_t_kernel<<<dim3(QKVN / 32, HH / 32), dim3(32, 8)>>>(
            w_qkv, wqh, wql, HH, QKVN);
        split_t_kernel<<<dim3(HH / 32, HH / 32), dim3(32, 8)>>>(
            w_o, woh, wol, HH, HH);
    }
    // 1) QKV projection
    gemm_bf16x3<<<dim3(QKVN / 128, M / 128), 256, GEMM_SMEM>>>(
        hidh, hidl, wqh, wql, qkv, M, QKVN, HH);
    // 2) pre-passes: Q rope+split; unified KV build (rope on new K)
    {
        int nq = BB * SS * NQ * 64;
        rope_split_q<<<(nq + 255) / 256, 256>>>(qkv, cosb, sinb, qh, ql);
        int nkv = BB * NKV * TT * 64;
        build_kv<<<(nkv + 255) / 256, 256>>>(qkv, kc, vc, cosb, sinb,
                                             kh, kl, vh, vl);
    }
    // 3) Flash attention on tensor cores
    flash_mma<<<dim3(SS / 64, NQ, BB), 128, FA_SMEM>>>(
        qh, ql, kh, kl, vh, vl, ath, atl);
    // 4) Output projection
    gemm_bf16x3<<<dim3(HH / 128, M / 128), 256, GEMM_SMEM>>>(
        ath, atl, woh, wol, out, M, HH, HH);
}

// round 5
// speedup vs baseline: 3.1034x; 1.0446x over previous
#include <cuda_runtime.h>
#include <cuda_bf16.h>
#include <math.h>
#include <stdint.h>

// Problem constants
#define BB   2
#define SS   1024
#define PP   1024
#define TT   (PP + SS)
#define HH   4096
#define NQ   32
#define NKV  8
#define DD   128
#define QKVN ((NQ + 2 * NKV) * DD)   // 6144
#define SCALE 0.08838834764831845f   // 1/sqrt(128)

// ---------------------------------------------------------------------------
// Scratch (device globals: no allocation allowed)
// ---------------------------------------------------------------------------
__device__ float g_qkv[BB * SS * QKVN];
__device__ __nv_bfloat16 g_hid_h[BB * SS * HH];
__device__ __nv_bfloat16 g_hid_l[BB * SS * HH];
__device__ __nv_bfloat16 g_wqkv_h[(size_t)QKVN * HH];   // transposed [N,K]
__device__ __nv_bfloat16 g_wqkv_l[(size_t)QKVN * HH];
__device__ __nv_bfloat16 g_wo_h[(size_t)HH * HH];       // transposed [N,K]
__device__ __nv_bfloat16 g_wo_l[(size_t)HH * HH];
__device__ __nv_bfloat16 g_attn_h[BB * SS * NQ * DD];
__device__ __nv_bfloat16 g_attn_l[BB * SS * NQ * DD];
// Q hi/lo [B][NQ][S][D]
__device__ __nv_bfloat16 g_q_h[(size_t)BB * NQ * SS * DD];
__device__ __nv_bfloat16 g_q_l[(size_t)BB * NQ * SS * DD];
// unified KV hi/lo [B][NKV][T][D]
__device__ __nv_bfloat16 g_k_h[(size_t)BB * NKV * TT * DD];
__device__ __nv_bfloat16 g_k_l[(size_t)BB * NKV * TT * DD];
__device__ __nv_bfloat16 g_v_h[(size_t)BB * NKV * TT * DD];
__device__ __nv_bfloat16 g_v_l[(size_t)BB * NKV * TT * DD];

// ---------------------------------------------------------------------------
// Low-level helpers (plain sm_80+ ISA)
// ---------------------------------------------------------------------------
__device__ __forceinline__ uint32_t smem_u32(const void* p) {
    uint32_t a;
    asm("{ .reg .u64 t; cvta.to.shared.u64 t, %1; cvt.u32.u64 %0, t; }"
        : "=r"(a) : "l"(p));
    return a;
}
__device__ __forceinline__ void cp16(uint32_t dst, const void* src) {
    asm volatile("cp.async.cg.shared.global [%0], [%1], 16;"
                 :: "r"(dst), "l"(src));
}
__device__ __forceinline__ void ldsm4(uint32_t* r, uint32_t a) {
    asm volatile("ldmatrix.sync.aligned.m8n8.x4.shared.b16 {%0,%1,%2,%3}, [%4];"
                 : "=r"(r[0]), "=r"(r[1]), "=r"(r[2]), "=r"(r[3]) : "r"(a));
}
__device__ __forceinline__ void ldsm4t(uint32_t* r, uint32_t a) {
    asm volatile("ldmatrix.sync.aligned.m8n8.x4.trans.shared.b16 {%0,%1,%2,%3}, [%4];"
                 : "=r"(r[0]), "=r"(r[1]), "=r"(r[2]), "=r"(r[3]) : "r"(a));
}
__device__ __forceinline__ void mma16816(float* c, const uint32_t* a,
                                         const uint32_t b0, const uint32_t b1) {
    asm volatile(
        "mma.sync.aligned.m16n8k16.row.col.f32.bf16.bf16.f32 "
        "{%0,%1,%2,%3}, {%4,%5,%6,%7}, {%8,%9}, {%0,%1,%2,%3};"
        : "+f"(c[0]), "+f"(c[1]), "+f"(c[2]), "+f"(c[3])
        : "r"(a[0]), "r"(a[1]), "r"(a[2]), "r"(a[3]), "r"(b0), "r"(b1));
}

// ---------------------------------------------------------------------------
// fp32 -> bf16 hi/lo split (same layout)
// ---------------------------------------------------------------------------
__global__ void split_kernel(const float* __restrict__ x,
                             __nv_bfloat16* __restrict__ xh,
                             __nv_bfloat16* __restrict__ xl, int n)
{
    int i = blockIdx.x * blockDim.x + threadIdx.x;
    if (i >= n) return;
    float v = x[i];
    __nv_bfloat16 hb = __float2bfloat16(v);
    xh[i] = hb;
    xl[i] = __float2bfloat16(v - __bfloat162float(hb));
}

// fp32 [R,C] -> bf16 hi/lo transposed [C,R]
__global__ void split_t_kernel(const float* __restrict__ x,
                               __nv_bfloat16* __restrict__ xh,
                               __nv_bfloat16* __restrict__ xl, int R, int C)
{
    __shared__ float t[32][33];
    int r0 = blockIdx.y * 32, c0 = blockIdx.x * 32;
    int tx = threadIdx.x, ty = threadIdx.y;
#pragma unroll
    for (int j = 0; j < 4; j++)
        t[ty + 8 * j][tx] = x[(size_t)(r0 + ty + 8 * j) * C + c0 + tx];
    __syncthreads();
#pragma unroll
    for (int j = 0; j < 4; j++) {
        float v = t[tx][ty + 8 * j];
        __nv_bfloat16 hb = __float2bfloat16(v);
        size_t o = (size_t)(c0 + ty + 8 * j) * R + r0 + tx;
        xh[o] = hb;
        xl[o] = __float2bfloat16(v - __bfloat162float(hb));
    }
}

// ---------------------------------------------------------------------------
// bf16x3 GEMM via mma.sync: C[M,N] fp32 = (Ah+Al)[M,K] @ (Bh+Bl)[N,K]^T
// 128x256x64 block tile, 8 warps (warp tile 64x64), cp.async double buffer,
// xor-swizzled smem rows (64 bf16 = 128B/row) for conflict-free ldmatrix.
// ---------------------------------------------------------------------------
#define AH_OFF 0
#define AL_OFF 16384
#define BH_OFF 32768
#define BL_OFF 65536
#define STAGE_B  98304
#define GEMM_SMEM (2 * STAGE_B)   // 196608

#define LOAD_STAGE(c, s) do {                                              \
    int _k0 = (c) * 64;                                                    \
    uint32_t _stb = smb + (s) * STAGE_B;                                   \
    _Pragma("unroll")                                                      \
    for (int _i = 0; _i < 4; _i++) {                                       \
        int _id = tid + _i * 256;                                          \
        int _row = _id >> 3, _ch = _id & 7;                                \
        uint32_t _sw = (_row << 7) + ((_ch ^ (_row & 7)) << 4);            \
        const size_t _go = (size_t)_row * K + _k0 + _ch * 8;               \
        cp16(_stb + AH_OFF + _sw, srcAh + _go);                            \
        cp16(_stb + AL_OFF + _sw, srcAl + _go);                            \
    }                                                                      \
    _Pragma("unroll")                                                      \
    for (int _i = 0; _i < 8; _i++) {                                       \
        int _id = tid + _i * 256;                                          \
        int _row = _id >> 3, _ch = _id & 7;                                \
        uint32_t _sw = (_row << 7) + ((_ch ^ (_row & 7)) << 4);            \
        const size_t _go = (size_t)_row * K + _k0 + _ch * 8;               \
        cp16(_stb + BH_OFF + _sw, srcBh + _go);                            \
        cp16(_stb + BL_OFF + _sw, srcBl + _go);                            \
    }                                                                      \
    asm volatile("cp.async.commit_group;");                                \
} while (0)

__global__ __launch_bounds__(256, 1) void gemm_bf16x3(
    const __nv_bfloat16* __restrict__ Ah, const __nv_bfloat16* __restrict__ Al,
    const __nv_bfloat16* __restrict__ Bh, const __nv_bfloat16* __restrict__ Bl,
    float* __restrict__ C, int M, int N, int K)
{
    extern __shared__ char sm[];
    const uint32_t smb = smem_u32(sm);
    const int tid = threadIdx.x;
    const int wid = tid >> 5, lane = tid & 31;
    const int bm = blockIdx.y * 128, bn = blockIdx.x * 256;
    const int wm = (wid & 1) * 64, wn = (wid >> 1) * 64;

    const __nv_bfloat16* srcAh = Ah + (size_t)bm * K;
    const __nv_bfloat16* srcAl = Al + (size_t)bm * K;
    const __nv_bfloat16* srcBh = Bh + (size_t)bn * K;
    const __nv_bfloat16* srcBl = Bl + (size_t)bn * K;

    float acc[4][8][4];
#pragma unroll
    for (int i = 0; i < 4; i++)
#pragma unroll
        for (int j = 0; j < 8; j++)
#pragma unroll
            for (int e = 0; e < 4; e++) acc[i][j][e] = 0.f;

    const int NC = K / 64;
    LOAD_STAGE(0, 0);

    for (int c = 0; c < NC; c++) {
        const int s = c & 1;
        if (c + 1 < NC) {
            LOAD_STAGE(c + 1, s ^ 1);
            asm volatile("cp.async.wait_group 1;");
        } else {
            asm volatile("cp.async.wait_group 0;");
        }
        __syncthreads();

        const uint32_t base = smb + s * STAGE_B;
#pragma unroll
        for (int ks = 0; ks < 4; ks++) {
            const int c0 = ks * 2 + (lane >> 4);
            uint32_t ah[4][4], al[4][4];
#pragma unroll
            for (int mi = 0; mi < 4; mi++) {
                int row = wm + mi * 16 + (lane & 15);
                uint32_t off = (row << 7) + ((c0 ^ (row & 7)) << 4);
                ldsm4(ah[mi], base + AH_OFF + off);
                ldsm4(al[mi], base + AL_OFF + off);
            }
#pragma unroll
            for (int ni = 0; ni < 4; ni++) {
                int row = wn + ni * 16 + (lane & 15);
                uint32_t off = (row << 7) + ((c0 ^ (row & 7)) << 4);
                uint32_t bh[4], bl[4];
                ldsm4(bh, base + BH_OFF + off);
                ldsm4(bl, base + BL_OFF + off);
#pragma unroll
                for (int mi = 0; mi < 4; mi++) {
#pragma unroll
                    for (int sel = 0; sel < 2; sel++) {
                        float* a = acc[mi][ni * 2 + sel];
                        mma16816(a, ah[mi], bh[sel], bh[sel + 2]);
                        mma16816(a, ah[mi], bl[sel], bl[sel + 2]);
                        mma16816(a, al[mi], bh[sel], bh[sel + 2]);
                    }
                }
            }
        }
        __syncthreads();
    }

    const int g = lane >> 2, t = lane & 3;
#pragma unroll
    for (int mi = 0; mi < 4; mi++) {
#pragma unroll
        for (int nj = 0; nj < 8; nj++) {
            const float* a = acc[mi][nj];
            int row = bm + wm + mi * 16 + g;
            int col = bn + wn + nj * 8 + t * 2;
            *(float2*)&C[(size_t)row * N + col] = make_float2(a[0], a[1]);
            *(float2*)&C[(size_t)(row + 8) * N + col] = make_float2(a[2], a[3]);
        }
    }
}

// ---------------------------------------------------------------------------
// Pre-pass 1: RoPE + scale + hi/lo split of Q -> [B][NQ][S][D]
// ---------------------------------------------------------------------------
__global__ void rope_split_q(const float* __restrict__ qkv,
                             const float* __restrict__ cosb,
                             const float* __restrict__ sinb,
                             __nv_bfloat16* __restrict__ qh,
                             __nv_bfloat16* __restrict__ ql)
{
    int idx = blockIdx.x * blockDim.x + threadIdx.x;
    const int total = BB * SS * NQ * 64;
    if (idx >= total) return;
    int d = idx & 63;
    int rest = idx >> 6;
    int h = rest % NQ;
    int s = (rest / NQ) % SS;
    int b = rest / (NQ * SS);
    const float* base = &qkv[((size_t)(b * SS + s)) * QKVN + h * DD];
    float x1 = base[d], x2 = base[d + 64];
    float c0 = cosb[s * DD + d],      s0 = sinb[s * DD + d];
    float c1 = cosb[s * DD + d + 64], s1 = sinb[s * DD + d + 64];
    float y1 = (x1 * c0 - x2 * s0) * SCALE;
    float y2 = (x2 * c1 + x1 * s1) * SCALE;
    size_t o = (((size_t)(b * NQ + h)) * SS + s) * DD + d;
    __nv_bfloat16 h1 = __float2bfloat16(y1);
    __nv_bfloat16 h2 = __float2bfloat16(y2);
    qh[o] = h1;       qh[o + 64] = h2;
    ql[o] = __float2bfloat16(y1 - __bfloat162float(h1));
    ql[o + 64] = __float2bfloat16(y2 - __bfloat162float(h2));
}

// ---------------------------------------------------------------------------
// Pre-pass 2: unified KV hi/lo [B][NKV][T][D]; RoPE on new K rows.
// ---------------------------------------------------------------------------
__global__ void build_kv(const float* __restrict__ qkv,
                         const float* __restrict__ kcache,
                         const float* __restrict__ vcache,
                         const float* __restrict__ cosb,
                         const float* __restrict__ sinb,
                         __nv_bfloat16* __restrict__ khp, __nv_bfloat16* __restrict__ klp,
                         __nv_bfloat16* __restrict__ vhp, __nv_bfloat16* __restrict__ vlp)
{
    int idx = blockIdx.x * blockDim.x + threadIdx.x;
    const int total = BB * NKV * TT * 64;
    if (idx >= total) return;
    int d = idx & 63;
    int rest = idx >> 6;
    int t = rest % TT;
    int kh = (rest / TT) % NKV;
    int b = rest / (TT * NKV);

    float k1, k2, v1, v2;
    if (t < PP) {
        size_t src = (((size_t)(b * PP + t)) * NKV + kh) * DD;
        k1 = kcache[src + d]; k2 = kcache[src + d + 64];
        v1 = vcache[src + d]; v2 = vcache[src + d + 64];
    } else {
        int s = t - PP;
        const float* base = &qkv[((size_t)(b * SS + s)) * QKVN];
        float x1 = base[(NQ + kh) * DD + d], x2 = base[(NQ + kh) * DD + d + 64];
        float c0 = cosb[s * DD + d],      s0 = sinb[s * DD + d];
        float c1 = cosb[s * DD + d + 64], s1 = sinb[s * DD + d + 64];
        k1 = x1 * c0 - x2 * s0;
        k2 = x2 * c1 + x1 * s1;
        v1 = base[(NQ + NKV + kh) * DD + d];
        v2 = base[(NQ + NKV + kh) * DD + d + 64];
    }
    size_t o = (((size_t)(b * NKV + kh)) * TT + t) * DD + d;
    __nv_bfloat16 a;
    a = __float2bfloat16(k1); khp[o] = a;      klp[o] = __float2bfloat16(k1 - __bfloat162float(a));
    a = __float2bfloat16(k2); khp[o + 64] = a; klp[o + 64] = __float2bfloat16(k2 - __bfloat162float(a));
    a = __float2bfloat16(v1); vhp[o] = a;      vlp[o] = __float2bfloat16(v1 - __bfloat162float(a));
    a = __float2bfloat16(v2); vhp[o + 64] = a; vlp[o + 64] = __float2bfloat16(v2 - __bfloat162float(a));
}

// ---------------------------------------------------------------------------
// Flash attention on tensor cores, bf16x3 for QK and PV (unchanged).
// ---------------------------------------------------------------------------
#define FA_SMEM (4 * 64 * 256)   // 65536

__global__ __launch_bounds__(128) void flash_mma(
    const __nv_bfloat16* __restrict__ qh_g, const __nv_bfloat16* __restrict__ ql_g,
    const __nv_bfloat16* __restrict__ kh_g, const __nv_bfloat16* __restrict__ kl_g,
    const __nv_bfloat16* __restrict__ vh_g, const __nv_bfloat16* __restrict__ vl_g,
    __nv_bfloat16* __restrict__ attnh, __nv_bfloat16* __restrict__ attnl)
{
    extern __shared__ char sm[];
    const uint32_t smb = smem_u32(sm);
    const uint32_t KHO = 0, KLO = 16384, VHO = 32768, VLO = 49152;
    const int tid = threadIdx.x, lane = tid & 31, w = tid >> 5;
    const int qi = blockIdx.x, h = blockIdx.y, b = blockIdx.z;
    const int sq0 = qi * 64;
    const int khd = h >> 2;
    const int g = lane >> 2, t4 = lane & 3;
    const int r0 = w * 16 + g, r1 = r0 + 8;

    uint32_t qfh[8][4], qfl[8][4];
    {
        const __nv_bfloat16* qbh = qh_g + (((size_t)(b * NQ + h)) * SS + sq0) * DD;
        const __nv_bfloat16* qbl = ql_g + (((size_t)(b * NQ + h)) * SS + sq0) * DD;
#pragma unroll
        for (int ks = 0; ks < 8; ks++) {
            int c0 = ks * 16 + 2 * t4;
            qfh[ks][0] = *(const uint32_t*)(qbh + r0 * DD + c0);
            qfh[ks][1] = *(const uint32_t*)(qbh + r1 * DD + c0);
            qfh[ks][2] = *(const uint32_t*)(qbh + r0 * DD + c0 + 8);
            qfh[ks][3] = *(const uint32_t*)(qbh + r1 * DD + c0 + 8);
            qfl[ks][0] = *(const uint32_t*)(qbl + r0 * DD + c0);
            qfl[ks][1] = *(const uint32_t*)(qbl + r1 * DD + c0);
            qfl[ks][2] = *(const uint32_t*)(qbl + r0 * DD + c0 + 8);
            qfl[ks][3] = *(const uint32_t*)(qbl + r1 * DD + c0 + 8);
        }
    }

    float oacc[16][4];
#pragma unroll
    for (int i = 0; i < 16; i++)
#pragma unroll
        for (int j = 0; j < 4; j++) oacc[i][j] = 0.f;
    float m0 = -1e30f, m1 = -1e30f, l0 = 0.f, l1 = 0.f;

    const size_t kvb = ((size_t)(b * NKV + khd)) * TT * DD;
    const int nt = qi + 1 + PP / 64;

    for (int kt = 0; kt < nt; kt++) {
        __syncthreads();
        {
            const __nv_bfloat16* srcs[4] = {
                kh_g + kvb + (size_t)kt * 64 * DD,
                kl_g + kvb + (size_t)kt * 64 * DD,
                vh_g + kvb + (size_t)kt * 64 * DD,
                vl_g + kvb + (size_t)kt * 64 * DD };
            const uint32_t offs[4] = { KHO, KLO, VHO, VLO };
#pragma unroll
            for (int a = 0; a < 4; a++) {
#pragma unroll
                for (int i = 0; i < 8; i++) {
                    int id = tid + i * 128;
                    int r = id >> 4, ch = id & 15;
                    cp16(smb + offs[a] + r * 256 + ((ch ^ (r & 7)) << 4),
                         srcs[a] + r * DD + ch * 8);
                }
            }
            asm volatile("cp.async.commit_group;");
            asm volatile("cp.async.wait_group 0;");
            __syncthreads();
        }

        float sacc[8][4];
#pragma unroll
        for (int j = 0; j < 8; j++)
#pragma unroll
            for (int e = 0; e < 4; e++) sacc[j][e] = 0.f;
#pragma unroll
        for (int ks = 0; ks < 8; ks++) {
            const int c0 = ks * 2 + (lane >> 4);
#pragma unroll
            for (int kg = 0; kg < 4; kg++) {
                int r = kg * 16 + (lane & 15);
                uint32_t off = r * 256 + ((c0 ^ (r & 7)) << 4);
                uint32_t kbh[4], kbl[4];
                ldsm4(kbh, smb + KHO + off);
                ldsm4(kbl, smb + KLO + off);
#pragma unroll
                for (int sel = 0; sel < 2; sel++) {
                    float* sj = sacc[kg * 2 + sel];
                    mma16816(sj, qfh[ks], kbh[sel], kbh[sel + 2]);
                    mma16816(sj, qfh[ks], kbl[sel], kbl[sel + 2]);
                    mma16816(sj, qfl[ks], kbh[sel], kbh[sel + 2]);
                }
            }
        }

        if (kt == nt - 1) {
#pragma unroll
            for (int j = 0; j < 8; j++) {
                int cb = j * 8 + 2 * t4;
                if (cb     > r0) sacc[j][0] = -1e30f;
                if (cb + 1 > r0) sacc[j][1] = -1e30f;
                if (cb     > r1) sacc[j][2] = -1e30f;
                if (cb + 1 > r1) sacc[j][3] = -1e30f;
            }
        }

        float mx0 = m0, mx1 = m1;
#pragma unroll
        for (int j = 0; j < 8; j++) {
            mx0 = fmaxf(mx0, fmaxf(sacc[j][0], sacc[j][1]));
            mx1 = fmaxf(mx1, fmaxf(sacc[j][2], sacc[j][3]));
        }
        mx0 = fmaxf(mx0, __shfl_xor_sync(0xffffffff, mx0, 1));
        mx0 = fmaxf(mx0, __shfl_xor_sync(0xffffffff, mx0, 2));
        mx1 = fmaxf(mx1, __shfl_xor_sync(0xffffffff, mx1, 1));
        mx1 = fmaxf(mx1, __shfl_xor_sync(0xffffffff, mx1, 2));
        float rs0 = __expf(m0 - mx0), rs1 = __expf(m1 - mx1);
        m0 = mx0; m1 = mx1;
        l0 *= rs0; l1 *= rs1;

        uint32_t pfh[4][4], pfl[4][4];
#pragma unroll
        for (int j = 0; j < 8; j++) {
            float p0 = __expf(sacc[j][0] - m0);
            float p1 = __expf(sacc[j][1] - m0);
            float p2 = __expf(sacc[j][2] - m1);
            float p3 = __expf(sacc[j][3] - m1);
            l0 += p0 + p1; l1 += p2 + p3;
            int kk = j >> 1, u = (j & 1) * 2;
            __nv_bfloat162 hA = __float22bfloat162_rn(make_float2(p0, p1));
            float2 bA = __bfloat1622float2(hA);
            __nv_bfloat162 lA = __float22bfloat162_rn(make_float2(p0 - bA.x, p1 - bA.y));
            __nv_bfloat162 hB = __float22bfloat162_rn(make_float2(p2, p3));
            float2 bB = __bfloat1622float2(hB);
            __nv_bfloat162 lB = __float22bfloat162_rn(make_float2(p2 - bB.x, p3 - bB.y));
            pfh[kk][u]     = *(uint32_t*)&hA;
            pfh[kk][u + 1] = *(uint32_t*)&hB;
            pfl[kk][u]     = *(uint32_t*)&lA;
            pfl[kk][u + 1] = *(uint32_t*)&lB;
        }

#pragma unroll
        for (int i = 0; i < 16; i++) {
            oacc[i][0] *= rs0; oacc[i][1] *= rs0;
            oacc[i][2] *= rs1; oacc[i][3] *= rs1;
        }

#pragma unroll
        for (int kk = 0; kk < 4; kk++) {
#pragma unroll
            for (int dg = 0; dg < 8; dg++) {
                int r = kk * 16 + (lane & 15);
                int c0 = dg * 2 + (lane >> 4);
                uint32_t off = r * 256 + ((c0 ^ (r & 7)) << 4);
                uint32_t vbh[4], vbl[4];
                ldsm4t(vbh, smb + VHO + off);
                ldsm4t(vbl, smb + VLO + off);
                float* oA = oacc[dg * 2];
                float* oB = oacc[dg * 2 + 1];
                mma16816(oA, pfh[kk], vbh[0], vbh[1]);
                mma16816(oA, pfh[kk], vbl[0], vbl[1]);
                mma16816(oA, pfl[kk], vbh[0], vbh[1]);
                mma16816(oB, pfh[kk], vbh[2], vbh[3]);
                mma16816(oB, pfh[kk], vbl[2], vbl[3]);
                mma16816(oB, pfl[kk], vbh[2], vbh[3]);
            }
        }
    }

    l0 += __shfl_xor_sync(0xffffffff, l0, 1);
    l0 += __shfl_xor_sync(0xffffffff, l0, 2);
    l1 += __shfl_xor_sync(0xffffffff, l1, 1);
    l1 += __shfl_xor_sync(0xffffffff, l1, 2);
    float inv0 = 1.f / l0, inv1 = 1.f / l1;

    size_t rowA = ((size_t)(b * SS + sq0 + r0)) * (NQ * DD) + h * DD;
    size_t rowB = ((size_t)(b * SS + sq0 + r1)) * (NQ * DD) + h * DD;
#pragma unroll
    for (int dt = 0; dt < 16; dt++) {
        int c = dt * 8 + 2 * t4;
        float v0 = oacc[dt][0] * inv0, v1 = oacc[dt][1] * inv0;
        float v2 = oacc[dt][2] * inv1, v3 = oacc[dt][3] * inv1;
        __nv_bfloat162 hA = __float22bfloat162_rn(make_float2(v0, v1));
        float2 bA = __bfloat1622float2(hA);
        __nv_bfloat162 lA = __float22bfloat162_rn(make_float2(v0 - bA.x, v1 - bA.y));
        __nv_bfloat162 hB = __float22bfloat162_rn(make_float2(v2, v3));
        float2 bB = __bfloat1622float2(hB);
        __nv_bfloat162 lB = __float22bfloat162_rn(make_float2(v2 - bB.x, v3 - bB.y));
        *(__nv_bfloat162*)&attnh[rowA + c] = hA;
        *(__nv_bfloat162*)&attnl[rowA + c] = lA;
        *(__nv_bfloat162*)&attnh[rowB + c] = hB;
        *(__nv_bfloat162*)&attnl[rowB + c] = lB;
    }
}

// ---------------------------------------------------------------------------
extern "C" void kernel_launch(void* const* d_in, const int* in_sizes, int n_in,
                              void* d_out, int out_size)
{
    const float* hidden = (const float*)d_in[0];
    const float* w_qkv  = (const float*)d_in[1];
    const float* w_o    = (const float*)d_in[2];
    const float* cosb   = (const float*)d_in[3];
    const float* sinb   = (const float*)d_in[4];
    const float* kc     = (const float*)d_in[5];
    const float* vc     = (const float*)d_in[6];
    float* out = (float*)d_out;

    float *qkv;
    __nv_bfloat16 *hidh, *hidl, *wqh, *wql, *woh, *wol, *ath, *atl;
    __nv_bfloat16 *qh, *ql, *kh, *kl, *vh, *vl;
    cudaGetSymbolAddress((void**)&qkv, g_qkv);
    cudaGetSymbolAddress((void**)&hidh, g_hid_h);
    cudaGetSymbolAddress((void**)&hidl, g_hid_l);
    cudaGetSymbolAddress((void**)&wqh, g_wqkv_h);
    cudaGetSymbolAddress((void**)&wql, g_wqkv_l);
    cudaGetSymbolAddress((void**)&woh, g_wo_h);
    cudaGetSymbolAddress((void**)&wol, g_wo_l);
    cudaGetSymbolAddress((void**)&ath, g_attn_h);
    cudaGetSymbolAddress((void**)&atl, g_attn_l);
    cudaGetSymbolAddress((void**)&qh, g_q_h);
    cudaGetSymbolAddress((void**)&ql, g_q_l);
    cudaGetSymbolAddress((void**)&kh, g_k_h);
    cudaGetSymbolAddress((void**)&kl, g_k_l);
    cudaGetSymbolAddress((void**)&vh, g_v_h);
    cudaGetSymbolAddress((void**)&vl, g_v_l);

    cudaFuncSetAttribute(gemm_bf16x3,
                         cudaFuncAttributeMaxDynamicSharedMemorySize, GEMM_SMEM);
    cudaFuncSetAttribute(flash_mma,
                         cudaFuncAttributeMaxDynamicSharedMemorySize, FA_SMEM);

    const int M = BB * SS;  // 2048

    // 0) hi/lo splits (+ weight transposes to [N,K])
    {
        int n = M * HH;
        split_kernel<<<(n + 255) / 256, 256>>>(hidden, hidh, hidl, n);
        split_t_kernel<<<dim3(QKVN / 32, HH / 32), dim3(32, 8)>>>(
            w_qkv, wqh, wql, HH, QKVN);
        split_t_kernel<<<dim3(HH / 32, HH / 32), dim3(32, 8)>>>(
            w_o, woh, wol, HH, HH);
    }
    // 1) QKV projection (128x256 tiles)
    gemm_bf16x3<<<dim3(QKVN / 256, M / 128), 256, GEMM_SMEM>>>(
        hidh, hidl, wqh, wql, qkv, M, QKVN, HH);
    // 2) pre-passes
    {
        int nq = BB * SS * NQ * 64;
        rope_split_q<<<(nq + 255) / 256, 256>>>(qkv, cosb, sinb, qh, ql);
        int nkv = BB * NKV * TT * 64;
        build_kv<<<(nkv + 255) / 256, 256>>>(qkv, kc, vc, cosb, sinb,
                                             kh, kl, vh, vl);
    }
    // 3) Flash attention
    flash_mma<<<dim3(SS / 64, NQ, BB), 128, FA_SMEM>>>(
        qh, ql, kh, kl, vh, vl, ath, atl);
    // 4) Output projection
    gemm_bf16x3<<<dim3(HH / 256, M / 128), 256, GEMM_SMEM>>>(
        ath, atl, woh, wol, out, M, HH, HH);
}